// round 5
// baseline (speedup 1.0000x reference)
#include <cuda_runtime.h>
#include <cstdint>

// Model_25855703122577: inputs [8192,784,1] f32, W_ih[30,1], W_hh[30,30],
// b_mod[30], W_lin[10,30], b_lin[10] -> out [8192,10] f32
#define RB    8192
#define RT    784
#define RH    30
#define RC    10
#define GRP   16        // threads per batch element
#define RPT   2         // hidden rows per thread (16*2 = 32 >= 30)
#define KPP   16        // k-pairs padded (15 real + 1 zero pad)
#define NCH   8         // LDS.128 chunks per h vector (8 * 2 pairs = 16)
#define TPB   32        // one warp per block
#define SLOTS 4         // batches per block: 2 groups * 2 per thread
#define HSTR  36        // floats per h slot (32 data + 4 bank shift)

typedef unsigned long long u64;

__device__ __forceinline__ u64 fmul2(u64 a, u64 b) {
    u64 d; asm("mul.rn.f32x2 %0, %1, %2;" : "=l"(d) : "l"(a), "l"(b)); return d;
}
__device__ __forceinline__ u64 ffma2(u64 a, u64 b, u64 c) {
    u64 d; asm("fma.rn.f32x2 %0, %1, %2, %3;" : "=l"(d) : "l"(a), "l"(b), "l"(c)); return d;
}
__device__ __forceinline__ void unpack2(u64 v, float& lo, float& hi) {
    asm("mov.b64 {%0, %1}, %2;" : "=f"(lo), "=f"(hi) : "l"(v));
}
__device__ __forceinline__ float modrelu(float z, float b) {
    float m = fmaxf(fabsf(z) + b, 0.0f);
    float s = copysignf(m, z);
    return (z == 0.0f) ? 0.0f : s;
}

// One recurrence step for 2 batch elements, 2 rows each.
// h vectors (32 floats incl. zero pads) read as 8 LDS.128 with 1-ahead prefetch.
__device__ __forceinline__ void rnn_step2(
    float xa, float xb,
    const u64 (&w)[RPT][KPP],
    const float (&wih)[RPT],
    const float (&bm)[RPT],
    const float* __restrict__ hsrcA, const float* __restrict__ hsrcB,
    float* __restrict__ hdstA, float* __restrict__ hdstB)
{
    const ulonglong2* ha = reinterpret_cast<const ulonglong2*>(hsrcA);
    const ulonglong2* hb = reinterpret_cast<const ulonglong2*>(hsrcB);

    ulonglong2 ra[2], rb[2];
    ra[0] = ha[0]; rb[0] = hb[0];

    u64 aA[RPT], aB[RPT];
    // chunk 0 (pairs 0,1), start the 4 chains with mul
    ra[1] = ha[1]; rb[1] = hb[1];
#pragma unroll
    for (int r = 0; r < RPT; r++) {
        aA[r] = fmul2(w[r][0], ra[0].x);
        aB[r] = fmul2(w[r][0], rb[0].x);
        aA[r] = ffma2(w[r][1], ra[0].y, aA[r]);
        aB[r] = ffma2(w[r][1], rb[0].y, aB[r]);
    }
#pragma unroll
    for (int i = 1; i < NCH; i++) {
        if (i + 1 < NCH) {                 // prefetch next chunk
            ra[(i + 1) & 1] = ha[i + 1];
            rb[(i + 1) & 1] = hb[i + 1];
        }
        const ulonglong2 va = ra[i & 1];
        const ulonglong2 vb = rb[i & 1];
#pragma unroll
        for (int r = 0; r < RPT; r++) {
            aA[r] = ffma2(w[r][2 * i], va.x, aA[r]);
            aB[r] = ffma2(w[r][2 * i], vb.x, aB[r]);
        }
#pragma unroll
        for (int r = 0; r < RPT; r++) {
            aA[r] = ffma2(w[r][2 * i + 1], va.y, aA[r]);
            aB[r] = ffma2(w[r][2 * i + 1], vb.y, aB[r]);
        }
    }

    float hva[RPT], hvb[RPT];
#pragma unroll
    for (int r = 0; r < RPT; r++) {
        float loA, hiA, loB, hiB;
        unpack2(aA[r], loA, hiA);
        unpack2(aB[r], loB, hiB);
        float zA = fmaf(xa, wih[r], loA + hiA);
        float zB = fmaf(xb, wih[r], loB + hiB);
        hva[r] = modrelu(zA, bm[r]);
        hvb[r] = modrelu(zB, bm[r]);
    }
    *reinterpret_cast<float2*>(hdstA) = make_float2(hva[0], hva[1]);
    *reinterpret_cast<float2*>(hdstB) = make_float2(hvb[0], hvb[1]);
    __syncwarp();
}

extern "C" __global__ void __launch_bounds__(TPB)
rnn_modrelu_kernel(const float* __restrict__ inputs,  // [B, T]
                   const float* __restrict__ W_ih,    // [H]
                   const float* __restrict__ W_hh,    // [H, H]
                   const float* __restrict__ b_mod,   // [H]
                   const float* __restrict__ W_lin,   // [C, H]
                   const float* __restrict__ b_lin,   // [C]
                   float* __restrict__ out)           // [B, C]
{
    __shared__ float hbuf[2][SLOTS][HSTR];

    const int tid = threadIdx.x;            // 0..31
    const int sub = tid & (GRP - 1);        // 0..15 row-slice
    const int g   = tid >> 4;               // 0..1 group
    const int sA  = g;                      // slots 0,1
    const int sB  = g + 2;                  // slots 2,3
    const int bA  = blockIdx.x * SLOTS + sA;
    const int bB  = blockIdx.x * SLOTS + sB;

    // ---- weight slice: 2 rows x 16 padded k-pairs = 64 regs ----
    u64 w[RPT][KPP];
    float wih[RPT], bm[RPT];
#pragma unroll
    for (int r = 0; r < RPT; r++) {
        const int row = sub * RPT + r;
        if (row < RH) {
            const u64* wr = reinterpret_cast<const u64*>(W_hh + row * RH);
#pragma unroll
            for (int p = 0; p < KPP - 1; p++) w[r][p] = wr[p];
            w[r][KPP - 1] = 0ULL;       // pad pair (h[30],h[31] are zero too)
            wih[r] = W_ih[row];
            bm[r]  = b_mod[row];
        } else {                        // pad rows 30,31
#pragma unroll
            for (int p = 0; p < KPP; p++) w[r][p] = 0ULL;
            wih[r] = 0.0f;
            bm[r]  = 0.0f;
        }
    }

    // h0 = 0 (all 32 floats per slot, including pads, written every step)
    *reinterpret_cast<float2*>(&hbuf[0][sA][sub * 2]) = make_float2(0, 0);
    *reinterpret_cast<float2*>(&hbuf[0][sB][sub * 2]) = make_float2(0, 0);
    __syncwarp();

    const float* xrA = inputs + (size_t)bA * RT;
    const float* xrB = inputs + (size_t)bB * RT;

#pragma unroll 1
    for (int t0 = 0; t0 < RT; t0 += 4) {
        const float4 x4a = *reinterpret_cast<const float4*>(xrA + t0);
        const float4 x4b = *reinterpret_cast<const float4*>(xrB + t0);
        rnn_step2(x4a.x, x4b.x, w, wih, bm,
                  &hbuf[0][sA][0], &hbuf[0][sB][0],
                  &hbuf[1][sA][sub * 2], &hbuf[1][sB][sub * 2]);
        rnn_step2(x4a.y, x4b.y, w, wih, bm,
                  &hbuf[1][sA][0], &hbuf[1][sB][0],
                  &hbuf[0][sA][sub * 2], &hbuf[0][sB][sub * 2]);
        rnn_step2(x4a.z, x4b.z, w, wih, bm,
                  &hbuf[0][sA][0], &hbuf[0][sB][0],
                  &hbuf[1][sA][sub * 2], &hbuf[1][sB][sub * 2]);
        rnn_step2(x4a.w, x4b.w, w, wih, bm,
                  &hbuf[1][sA][0], &hbuf[1][sB][0],
                  &hbuf[0][sA][sub * 2], &hbuf[0][sB][sub * 2]);
    }
    // T=784 even -> final h in buffer 0

    // ---- fused classifier: out[b][c] = h . W_lin[c] + b_lin[c] ----
#pragma unroll 1
    for (int pass = 0; pass < 2; pass++) {
        const int slot = (pass == 0) ? sA : sB;
        const int b    = (pass == 0) ? bA : bB;
        const float* hf = &hbuf[0][slot][0];
        if (sub < RC) {
            float acc = b_lin[sub];
            const float* wl = W_lin + sub * RH;
#pragma unroll
            for (int k = 0; k < RH; k++) acc = fmaf(hf[k], wl[k], acc);
            out[(size_t)b * RC + sub] = acc;
        }
    }
}

extern "C" void kernel_launch(void* const* d_in, const int* in_sizes, int n_in,
                              void* d_out, int out_size) {
    const float* inputs = (const float*)d_in[0];
    const float* W_ih   = (const float*)d_in[1];
    const float* W_hh   = (const float*)d_in[2];
    const float* b_mod  = (const float*)d_in[3];
    const float* W_lin  = (const float*)d_in[4];
    const float* b_lin  = (const float*)d_in[5];
    float* out = (float*)d_out;

    dim3 grid(RB / SLOTS);   // 2048 one-warp blocks -> ~14 warps/SM, single wave
    dim3 block(TPB);
    rnn_modrelu_kernel<<<grid, block>>>(inputs, W_ih, W_hh, b_mod,
                                        W_lin, b_lin, out);
}